// round 1
// baseline (speedup 1.0000x reference)
#include <cuda_runtime.h>
#include <cstdint>

// Problem constants
constexpr int BATCH = 16384;
constexpr int HID   = 512;
constexpr int NSTEP = 127;          // SIM_TIME - 1
#define NELEM (16384 * 512)

// Scratch state (device globals; no allocations allowed)
__device__ float g_h0[NELEM];       // layer-0 drive, time-invariant
__device__ float g_m0[NELEM];
__device__ float g_s1[NELEM];
__device__ float g_m1[NELEM];
__device__ float g_s2[NELEM];
__device__ float g_spk0[NELEM];
__device__ float g_spk1[NELEM];

// ---- packed f32x2 helpers (FFMA2: 2x fp32 FMA throughput, PTX-only) ----
__device__ __forceinline__ unsigned long long pack2(float lo, float hi) {
    unsigned long long r;
    asm("mov.b64 %0, {%1, %2};" : "=l"(r) : "f"(lo), "f"(hi));
    return r;
}
__device__ __forceinline__ void unpack2(unsigned long long v, float& lo, float& hi) {
    asm("mov.b64 {%0, %1}, %2;" : "=f"(lo), "=f"(hi) : "l"(v));
}
__device__ __forceinline__ void fma2(unsigned long long& d, unsigned long long a,
                                     unsigned long long b) {
    asm("fma.rn.f32x2 %0, %1, %2, %0;" : "+l"(d) : "l"(a), "l"(b));
}

// ---- zero-init states + output (d_out is poisoned to 0xAA) ----
__global__ void zero_kernel(float4* __restrict__ out) {
    int i = blockIdx.x * blockDim.x + threadIdx.x;   // over NELEM/4 float4s
    float4 z = make_float4(0.f, 0.f, 0.f, 0.f);
    ((float4*)g_m0)[i] = z;
    ((float4*)g_s1)[i] = z;
    ((float4*)g_m1)[i] = z;
    ((float4*)g_s2)[i] = z;
    out[i] = z;
}

// ---- layer-0 LIF update: m0 = beta*m0 + h0; spike; reset ----
__global__ void step0_kernel() {
    int i = blockIdx.x * blockDim.x + threadIdx.x;   // over NELEM/4 float4s
    float4 h = ((const float4*)g_h0)[i];
    float4 m = ((const float4*)g_m0)[i];
    m.x = 0.85f * m.x + h.x;
    m.y = 0.85f * m.y + h.y;
    m.z = 0.85f * m.z + h.z;
    m.w = 0.85f * m.w + h.w;
    float4 spk;
    spk.x = (m.x > 1.0f) ? 1.0f : 0.0f;  m.x = (m.x > 1.0f) ? 0.0f : m.x;
    spk.y = (m.y > 1.0f) ? 1.0f : 0.0f;  m.y = (m.y > 1.0f) ? 0.0f : m.y;
    spk.z = (m.z > 1.0f) ? 1.0f : 0.0f;  m.z = (m.z > 1.0f) ? 0.0f : m.z;
    spk.w = (m.w > 1.0f) ? 1.0f : 0.0f;  m.w = (m.w > 1.0f) ? 0.0f : m.w;
    ((float4*)g_m0)[i]   = m;
    ((float4*)g_spk0)[i] = spk;
}

// ---- fused GEMM + LIF epilogue ----
// MODE 0: h0 = relu_concat(inputs) @ W0 (K=256), plain store to g_h0
// MODE 1: h = spk0 @ W1; s1 = a*s1+h; m1 = b*m1+s1; spike -> g_spk1; reset
// MODE 2: h = spk1 @ W2; s2 = a*s2+h; m2 = b*m2+s2 (m2 lives in d_out)
template <int MODE>
__global__ __launch_bounds__(256)
void gemm_kernel(const float* __restrict__ Aext,
                 const float* __restrict__ W,
                 float* __restrict__ Mext) {
    constexpr int K  = (MODE == 0) ? 256 : 512;
    constexpr int KT = 8;
    constexpr int NK = K / KT;

    __shared__ float As[2][KT][128];
    __shared__ float Bs[2][KT][128];

    const float* A = (MODE == 0) ? Aext : ((MODE == 1) ? g_spk0 : g_spk1);

    const int row0 = blockIdx.x * 128;
    const int col0 = blockIdx.y * 128;
    const int tid  = threadIdx.x;
    const int tx   = tid & 15;     // 16 col-threads
    const int ty   = tid >> 4;     // 16 row-threads

    // staging indices: A tile 128x8 (one float4/thread), B tile 8x128 (one float4/thread)
    const int ar = tid >> 1;            // 0..127 (row within A tile)
    const int aq = (tid & 1) * 4;       // 0 or 4 (k offset within tile)
    const int bk = tid >> 5;            // 0..7
    const int bj = (tid & 31) * 4;      // 0..124

    unsigned long long acc[8][4];
#pragma unroll
    for (int i = 0; i < 8; i++)
#pragma unroll
        for (int j = 0; j < 4; j++) acc[i][j] = 0ULL;

    float4 ra, rb;

    auto LOADG = [&](int k0) {
        if (MODE == 0) {
            // x[b][kk] = kk<128 ? relu(in[b][kk]) : relu(-in[b][kk-128])
            int kk = k0 + aq;
            if (kk < 128) {
                float4 v = *(const float4*)(Aext + (size_t)(row0 + ar) * 128 + kk);
                ra.x = fmaxf(v.x, 0.f); ra.y = fmaxf(v.y, 0.f);
                ra.z = fmaxf(v.z, 0.f); ra.w = fmaxf(v.w, 0.f);
            } else {
                float4 v = *(const float4*)(Aext + (size_t)(row0 + ar) * 128 + (kk - 128));
                ra.x = fmaxf(-v.x, 0.f); ra.y = fmaxf(-v.y, 0.f);
                ra.z = fmaxf(-v.z, 0.f); ra.w = fmaxf(-v.w, 0.f);
            }
        } else {
            ra = *(const float4*)(A + (size_t)(row0 + ar) * 512 + k0 + aq);
        }
        rb = *(const float4*)(W + (size_t)(k0 + bk) * 512 + col0 + bj);
    };
    auto STORES = [&](int buf) {
        As[buf][aq + 0][ar] = ra.x;
        As[buf][aq + 1][ar] = ra.y;
        As[buf][aq + 2][ar] = ra.z;
        As[buf][aq + 3][ar] = ra.w;
        *(float4*)&Bs[buf][bk][bj] = rb;
    };

    LOADG(0);
    STORES(0);
    __syncthreads();

    for (int kt = 0; kt < NK; kt++) {
        const int buf = kt & 1;
        if (kt + 1 < NK) LOADG((kt + 1) * KT);
#pragma unroll
        for (int k = 0; k < KT; k++) {
            float4 a0 = *(const float4*)&As[buf][k][ty * 8];
            float4 a1 = *(const float4*)&As[buf][k][ty * 8 + 4];
            float4 b0 = *(const float4*)&Bs[buf][k][tx * 8];
            float4 b1 = *(const float4*)&Bs[buf][k][tx * 8 + 4];
            unsigned long long b2[4];
            b2[0] = pack2(b0.x, b0.y);
            b2[1] = pack2(b0.z, b0.w);
            b2[2] = pack2(b1.x, b1.y);
            b2[3] = pack2(b1.z, b1.w);
            float av[8] = {a0.x, a0.y, a0.z, a0.w, a1.x, a1.y, a1.z, a1.w};
#pragma unroll
            for (int i = 0; i < 8; i++) {
                unsigned long long a2 = pack2(av[i], av[i]);
#pragma unroll
                for (int j = 0; j < 4; j++) fma2(acc[i][j], a2, b2[j]);
            }
        }
        if (kt + 1 < NK) STORES(buf ^ 1);
        __syncthreads();
    }

    // ---- fused epilogue ----
    const int r0 = row0 + ty * 8;
    const int c0 = col0 + tx * 8;
#pragma unroll
    for (int i = 0; i < 8; i++) {
        float h[8];
#pragma unroll
        for (int j = 0; j < 4; j++) unpack2(acc[i][j], h[2 * j], h[2 * j + 1]);
        size_t base = (size_t)(r0 + i) * 512 + c0;

        if (MODE == 0) {
            *(float4*)&g_h0[base]     = make_float4(h[0], h[1], h[2], h[3]);
            *(float4*)&g_h0[base + 4] = make_float4(h[4], h[5], h[6], h[7]);
        } else {
            float* S = (MODE == 1) ? g_s1 : g_s2;
            float* M = (MODE == 1) ? g_m1 : Mext;
            float4 sv0 = *(const float4*)&S[base];
            float4 sv1 = *(const float4*)&S[base + 4];
            float4 mv0 = *(const float4*)&M[base];
            float4 mv1 = *(const float4*)&M[base + 4];
            float s[8] = {sv0.x, sv0.y, sv0.z, sv0.w, sv1.x, sv1.y, sv1.z, sv1.w};
            float m[8] = {mv0.x, mv0.y, mv0.z, mv0.w, mv1.x, mv1.y, mv1.z, mv1.w};
            float spk[8];
#pragma unroll
            for (int e = 0; e < 8; e++) {
                s[e] = 0.9f * s[e] + h[e];
                m[e] = 0.85f * m[e] + s[e];
                if (MODE == 1) {
                    spk[e] = (m[e] > 1.0f) ? 1.0f : 0.0f;
                    m[e]   = (m[e] > 1.0f) ? 0.0f : m[e];
                }
            }
            *(float4*)&S[base]     = make_float4(s[0], s[1], s[2], s[3]);
            *(float4*)&S[base + 4] = make_float4(s[4], s[5], s[6], s[7]);
            *(float4*)&M[base]     = make_float4(m[0], m[1], m[2], m[3]);
            *(float4*)&M[base + 4] = make_float4(m[4], m[5], m[6], m[7]);
            if (MODE == 1) {
                *(float4*)&g_spk1[base]     = make_float4(spk[0], spk[1], spk[2], spk[3]);
                *(float4*)&g_spk1[base + 4] = make_float4(spk[4], spk[5], spk[6], spk[7]);
            }
        }
    }
}

extern "C" void kernel_launch(void* const* d_in, const int* in_sizes, int n_in,
                              void* d_out, int out_size) {
    (void)in_sizes; (void)n_in; (void)out_size;
    const float* inp = (const float*)d_in[0];   // [16384, 128]
    const float* W0  = (const float*)d_in[1];   // [256, 512]
    const float* W1  = (const float*)d_in[2];   // [512, 512]
    const float* W2  = (const float*)d_in[3];   // [512, 512]
    float* out = (float*)d_out;                 // m2 state, [16384, 512]

    const int EW_BLOCKS = (NELEM / 4) / 256;    // 8192

    zero_kernel<<<EW_BLOCKS, 256>>>((float4*)out);
    // time-invariant layer-0 drive: h0 = relu_concat(inputs) @ W0
    gemm_kernel<0><<<dim3(BATCH / 128, HID / 128), 256>>>(inp, W0, nullptr);

    for (int t = 0; t < NSTEP; t++) {
        step0_kernel<<<EW_BLOCKS, 256>>>();
        gemm_kernel<1><<<dim3(BATCH / 128, HID / 128), 256>>>(nullptr, W1, nullptr);
        gemm_kernel<2><<<dim3(BATCH / 128, HID / 128), 256>>>(nullptr, W2, out);
    }
}

// round 3
// speedup vs baseline: 1.7522x; 1.7522x over previous
#include <cuda_runtime.h>
#include <cuda_bf16.h>
#include <cstdint>

// ============================================================
// 3-layer SNN. B=16384, H=512, 127 steps.
// h0 = relu_concat(x) @ W0 is time-invariant (computed once, fp32 SIMT).
// Per step: spk0@W1 + LIF -> spk1 ; spk1@W2 + LIF -> m2 (+ fused layer-0 LIF).
// GEMM engine: mma.sync m16n8k16 bf16 (HMMA; tcgen05 unavailable — harness
// ptxas targets sm_103 base, which rejects all tcgen05/.cta_group features).
// Precision: exact 3-way bf16 split of W; spikes {0,1} exact in bf16;
// fp32 accumulate => fp32-class total error.
// ============================================================

constexpr int BATCH = 16384;
constexpr int NSTEP = 127;
#define NELEM (16384 * 512)

// ---- device state (no allocations allowed) ----
__device__ float g_h0[NELEM];
__device__ float g_m0[NELEM];
__device__ float g_s1[NELEM];
__device__ float g_m1[NELEM];
__device__ float g_s2[NELEM];
__device__ __nv_bfloat16 g_spk0[NELEM];
__device__ __nv_bfloat16 g_spk1[NELEM];
// W transposed to [N][K] K-contiguous, 3-way exact bf16 split
__device__ __nv_bfloat16 g_W1t[3][512 * 512];
__device__ __nv_bfloat16 g_W2t[3][512 * 512];

// ---- PTX helpers (all sm_80-class, valid at sm_103 base target) ----
__device__ __forceinline__ uint32_t smem_to_u32(const void* p) {
    uint32_t a;
    asm("{ .reg .u64 t; cvta.to.shared.u64 t, %1; cvt.u32.u64 %0, t; }"
        : "=r"(a) : "l"(p));
    return a;
}
__device__ __forceinline__ void cp16(uint32_t dst, const void* src) {
    asm volatile("cp.async.cg.shared.global [%0], [%1], 16;"
                 :: "r"(dst), "l"(src) : "memory");
}
#define CP_COMMIT() asm volatile("cp.async.commit_group;" ::: "memory")
#define CP_WAIT(N)  asm volatile("cp.async.wait_group %0;" :: "n"(N) : "memory")

__device__ __forceinline__ void ldm4(uint32_t& r0, uint32_t& r1, uint32_t& r2,
                                     uint32_t& r3, uint32_t addr) {
    asm volatile("ldmatrix.sync.aligned.m8n8.x4.shared.b16 {%0,%1,%2,%3}, [%4];"
                 : "=r"(r0), "=r"(r1), "=r"(r2), "=r"(r3) : "r"(addr));
}
__device__ __forceinline__ void mma16816(float* c, const uint32_t* a,
                                         uint32_t b0, uint32_t b1) {
    asm volatile(
        "mma.sync.aligned.m16n8k16.row.col.f32.bf16.bf16.f32 "
        "{%0,%1,%2,%3}, {%4,%5,%6,%7}, {%8,%9}, {%0,%1,%2,%3};"
        : "+f"(c[0]), "+f"(c[1]), "+f"(c[2]), "+f"(c[3])
        : "r"(a[0]), "r"(a[1]), "r"(a[2]), "r"(a[3]), "r"(b0), "r"(b1));
}
#define SWZ(x) ((x) ^ (((x) >> 3) & 0x70))

// ============================================================
// one-time kernels
// ============================================================
__global__ void zero_kernel(float4* __restrict__ out) {
    int i = blockIdx.x * blockDim.x + threadIdx.x;
    float4 z = make_float4(0.f, 0.f, 0.f, 0.f);
    ((float4*)g_m0)[i] = z;
    ((float4*)g_s1)[i] = z;
    ((float4*)g_m1)[i] = z;
    ((float4*)g_s2)[i] = z;
    out[i] = z;
}

// exact 3-way bf16 split + transpose of W [512K x 512N] -> Wt[3][N][K]
template <int WHICH>
__global__ void prep_kernel(const float* __restrict__ Wsrc) {
    int idx = blockIdx.x * blockDim.x + threadIdx.x;  // over 512*512
    int k = idx >> 9, n = idx & 511;
    float w = Wsrc[idx];
    __nv_bfloat16 hi = __float2bfloat16(w);
    float r1 = w - __bfloat162float(hi);
    __nv_bfloat16 mid = __float2bfloat16(r1);
    float r2 = r1 - __bfloat162float(mid);
    __nv_bfloat16 lo = __float2bfloat16(r2);
    __nv_bfloat16 (*dst)[512 * 512] = (WHICH == 1) ? g_W1t : g_W2t;
    int t = n * 512 + k;
    dst[0][t] = hi;
    dst[1][t] = mid;
    dst[2][t] = lo;
}

// standalone layer-0 LIF (t=0 only; later fused into gemm_mma<2>)
__global__ void step0_kernel() {
    int i = blockIdx.x * blockDim.x + threadIdx.x;
    float4 h = ((const float4*)g_h0)[i];
    float4 m = ((const float4*)g_m0)[i];
    m.x = 0.85f * m.x + h.x;  m.y = 0.85f * m.y + h.y;
    m.z = 0.85f * m.z + h.z;  m.w = 0.85f * m.w + h.w;
    float sx = (m.x > 1.f) ? 1.f : 0.f;  m.x = (m.x > 1.f) ? 0.f : m.x;
    float sy = (m.y > 1.f) ? 1.f : 0.f;  m.y = (m.y > 1.f) ? 0.f : m.y;
    float sz = (m.z > 1.f) ? 1.f : 0.f;  m.z = (m.z > 1.f) ? 0.f : m.z;
    float sw = (m.w > 1.f) ? 1.f : 0.f;  m.w = (m.w > 1.f) ? 0.f : m.w;
    ((float4*)g_m0)[i] = m;
    __nv_bfloat162* sp = (__nv_bfloat162*)(g_spk0 + 4 * (size_t)i);
    sp[0] = __floats2bfloat162_rn(sx, sy);
    sp[1] = __floats2bfloat162_rn(sz, sw);
}

// ============================================================
// layer-0 drive: h0 = relu_concat(inputs) @ W0 (fp32, runs once)
// ============================================================
__global__ __launch_bounds__(256)
void gemm0_kernel(const float* __restrict__ Aext, const float* __restrict__ W) {
    constexpr int KT = 8, NK = 256 / KT;
    __shared__ float As[2][KT][128];
    __shared__ float Bs[2][KT][128];
    const int row0 = blockIdx.x * 128, col0 = blockIdx.y * 128;
    const int tid = threadIdx.x;
    const int tx = tid & 15, ty = tid >> 4;
    const int ar = tid >> 1, aq = (tid & 1) * 4;
    const int bk = tid >> 5, bj = (tid & 31) * 4;

    float acc[8][8];
#pragma unroll
    for (int i = 0; i < 8; i++)
#pragma unroll
        for (int j = 0; j < 8; j++) acc[i][j] = 0.f;

    float4 ra, rb;
    auto LOADG = [&](int k0) {
        int kk = k0 + aq;
        if (kk < 128) {
            float4 v = *(const float4*)(Aext + (size_t)(row0 + ar) * 128 + kk);
            ra.x = fmaxf(v.x, 0.f); ra.y = fmaxf(v.y, 0.f);
            ra.z = fmaxf(v.z, 0.f); ra.w = fmaxf(v.w, 0.f);
        } else {
            float4 v = *(const float4*)(Aext + (size_t)(row0 + ar) * 128 + (kk - 128));
            ra.x = fmaxf(-v.x, 0.f); ra.y = fmaxf(-v.y, 0.f);
            ra.z = fmaxf(-v.z, 0.f); ra.w = fmaxf(-v.w, 0.f);
        }
        rb = *(const float4*)(W + (size_t)(k0 + bk) * 512 + col0 + bj);
    };
    auto STORES = [&](int buf) {
        As[buf][aq + 0][ar] = ra.x; As[buf][aq + 1][ar] = ra.y;
        As[buf][aq + 2][ar] = ra.z; As[buf][aq + 3][ar] = ra.w;
        *(float4*)&Bs[buf][bk][bj] = rb;
    };

    LOADG(0); STORES(0); __syncthreads();
    for (int kt = 0; kt < NK; kt++) {
        const int buf = kt & 1;
        if (kt + 1 < NK) LOADG((kt + 1) * KT);
#pragma unroll
        for (int k = 0; k < KT; k++) {
            float4 a0 = *(const float4*)&As[buf][k][ty * 8];
            float4 a1 = *(const float4*)&As[buf][k][ty * 8 + 4];
            float4 b0 = *(const float4*)&Bs[buf][k][tx * 8];
            float4 b1 = *(const float4*)&Bs[buf][k][tx * 8 + 4];
            float av[8] = {a0.x, a0.y, a0.z, a0.w, a1.x, a1.y, a1.z, a1.w};
            float bv[8] = {b0.x, b0.y, b0.z, b0.w, b1.x, b1.y, b1.z, b1.w};
#pragma unroll
            for (int i = 0; i < 8; i++)
#pragma unroll
                for (int j = 0; j < 8; j++) acc[i][j] = fmaf(av[i], bv[j], acc[i][j]);
        }
        if (kt + 1 < NK) STORES(buf ^ 1);
        __syncthreads();
    }
    const int r0 = row0 + ty * 8, c0 = col0 + tx * 8;
#pragma unroll
    for (int i = 0; i < 8; i++) {
        size_t base = (size_t)(r0 + i) * 512 + c0;
        *(float4*)&g_h0[base]     = make_float4(acc[i][0], acc[i][1], acc[i][2], acc[i][3]);
        *(float4*)&g_h0[base + 4] = make_float4(acc[i][4], acc[i][5], acc[i][6], acc[i][7]);
    }
}

// ============================================================
// HMMA GEMM + fused LIF epilogue
// Tile: M=128 x N=128, K=512 in 8 chunks of 64, 3 bf16 splits of W.
// 8 warps: warp_m = wid&3 (32 rows), warp_n = wid>>2 (64 cols).
// smem: 2 stages x (A 16KB + 3x B 16KB) = 128KB; C staged in stage0.
// ============================================================
constexpr int STAGE_BYTES = 65536;
constexpr int SMEM_NEED   = 2 * STAGE_BYTES;

template <int MODE>
__global__ __launch_bounds__(256, 1)
void gemm_mma(float* __restrict__ Mext) {
    extern __shared__ char smem[];
    const int tid = threadIdx.x;
    const int wid = tid >> 5, lane = tid & 31;
    const int warp_m = wid & 3, warp_n = wid >> 2;
    const int row0 = blockIdx.x * 128, col0 = blockIdx.y * 128;

    const __nv_bfloat16* A = (MODE == 1) ? g_spk0 : g_spk1;
    const __nv_bfloat16* W = (MODE == 1) ? &g_W1t[0][0] : &g_W2t[0][0];

    const uint32_t sb = smem_to_u32(smem);

    // ---- async tile staging (A[128][64], B[3][128][64], SW-swizzled) ----
    auto load_chunk = [&](int c, int s) {
        const uint32_t ap = sb + s * STAGE_BYTES;
        const uint32_t bp = ap + 16384;
        const int k0 = c * 64;
#pragma unroll
        for (int j = 0; j < 4; j++) {
            int i = tid + j * 256;
            int r = i >> 3, q = i & 7;
            cp16(ap + SWZ(r * 128 + q * 16),
                 A + (size_t)(row0 + r) * 512 + k0 + q * 8);
        }
#pragma unroll
        for (int j = 0; j < 12; j++) {
            int i = tid + j * 256;
            int sp = i >> 10, rem = i & 1023;
            int n = rem >> 3, q = rem & 7;
            cp16(bp + sp * 16384 + SWZ(n * 128 + q * 16),
                 W + (size_t)sp * 262144 + (size_t)(col0 + n) * 512 + k0 + q * 8);
        }
        CP_COMMIT();
    };

    float acc[2][8][4];
#pragma unroll
    for (int mt = 0; mt < 2; mt++)
#pragma unroll
        for (int nb = 0; nb < 8; nb++)
#pragma unroll
            for (int e = 0; e < 4; e++) acc[mt][nb][e] = 0.f;

    load_chunk(0, 0);

    const int mat = lane >> 3, mrr = lane & 7;

    for (int c = 0; c < 8; c++) {
        const int s = c & 1;
        if (c + 1 < 8) { load_chunk(c + 1, s ^ 1); CP_WAIT(1); }
        else           { CP_WAIT(0); }
        __syncthreads();

        const uint32_t ab = sb + s * STAGE_BYTES;
        const uint32_t bb = ab + 16384;
#pragma unroll
        for (int k16 = 0; k16 < 4; k16++) {
            const int k0 = k16 * 16;
            uint32_t a[2][4];
#pragma unroll
            for (int mt = 0; mt < 2; mt++) {
                int row = warp_m * 32 + mt * 16 + (mat & 1) * 8 + mrr;
                int kk  = k0 + (mat >> 1) * 8;
                ldm4(a[mt][0], a[mt][1], a[mt][2], a[mt][3],
                     ab + SWZ(row * 128 + kk * 2));
            }
#pragma unroll
            for (int sp = 0; sp < 3; sp++) {
                uint32_t b[4][4];
#pragma unroll
                for (int nt = 0; nt < 4; nt++) {
                    int n  = warp_n * 64 + nt * 16 + (mat >> 1) * 8 + mrr;
                    int kk = k0 + (mat & 1) * 8;
                    ldm4(b[nt][0], b[nt][1], b[nt][2], b[nt][3],
                         bb + sp * 16384 + SWZ(n * 128 + kk * 2));
                }
#pragma unroll
                for (int mt = 0; mt < 2; mt++)
#pragma unroll
                    for (int nb = 0; nb < 8; nb++)
                        mma16816(acc[mt][nb], a[mt],
                                 b[nb >> 1][(nb & 1) * 2],
                                 b[nb >> 1][(nb & 1) * 2 + 1]);
            }
        }
        __syncthreads();
    }

    // ---- stage C through smem (stride 132 floats -> conflict-free) ----
    float* C = (float*)smem;
#pragma unroll
    for (int mt = 0; mt < 2; mt++)
#pragma unroll
        for (int nb = 0; nb < 8; nb++) {
            int row = warp_m * 32 + mt * 16 + (lane >> 2);
            int col = warp_n * 64 + nb * 8 + (lane & 3) * 2;
            *(float2*)&C[row * 132 + col]       = make_float2(acc[mt][nb][0], acc[mt][nb][1]);
            *(float2*)&C[(row + 8) * 132 + col] = make_float2(acc[mt][nb][2], acc[mt][nb][3]);
        }
    __syncthreads();

    // ---- fused LIF epilogue (coalesced) ----
    float* S = (MODE == 1) ? g_s1 : g_s2;
    float* M = (MODE == 1) ? g_m1 : Mext;
#pragma unroll
    for (int j = 0; j < 16; j++) {
        int v = tid + j * 256;                 // 4096 float4 groups
        int rr = v >> 5, cc = (v & 31) << 2;
        float4 h = *(const float4*)&C[rr * 132 + cc];
        size_t ix = (size_t)(row0 + rr) * 512 + col0 + cc;
        float4 sv = *(const float4*)(S + ix);
        float4 mv = *(const float4*)(M + ix);
        sv.x = 0.9f * sv.x + h.x;  mv.x = 0.85f * mv.x + sv.x;
        sv.y = 0.9f * sv.y + h.y;  mv.y = 0.85f * mv.y + sv.y;
        sv.z = 0.9f * sv.z + h.z;  mv.z = 0.85f * mv.z + sv.z;
        sv.w = 0.9f * sv.w + h.w;  mv.w = 0.85f * mv.w + sv.w;
        if (MODE == 1) {
            float px = (mv.x > 1.f) ? 1.f : 0.f;  mv.x = (mv.x > 1.f) ? 0.f : mv.x;
            float py = (mv.y > 1.f) ? 1.f : 0.f;  mv.y = (mv.y > 1.f) ? 0.f : mv.y;
            float pz = (mv.z > 1.f) ? 1.f : 0.f;  mv.z = (mv.z > 1.f) ? 0.f : mv.z;
            float pw = (mv.w > 1.f) ? 1.f : 0.f;  mv.w = (mv.w > 1.f) ? 0.f : mv.w;
            __nv_bfloat162* sp2 = (__nv_bfloat162*)(g_spk1 + ix);
            sp2[0] = __floats2bfloat162_rn(px, py);
            sp2[1] = __floats2bfloat162_rn(pz, pw);
        }
        *(float4*)(S + ix) = sv;
        *(float4*)(M + ix) = mv;
    }

    // ---- MODE 2: layer-0 LIF for the NEXT step over this tile ----
    if (MODE == 2) {
#pragma unroll
        for (int j = 0; j < 16; j++) {
            int v = tid + j * 256;
            int rr = v >> 5, cc = (v & 31) << 2;
            size_t ix = (size_t)(row0 + rr) * 512 + col0 + cc;
            float4 h = *(const float4*)(g_h0 + ix);
            float4 m = *(const float4*)(g_m0 + ix);
            m.x = 0.85f * m.x + h.x;  m.y = 0.85f * m.y + h.y;
            m.z = 0.85f * m.z + h.z;  m.w = 0.85f * m.w + h.w;
            float px = (m.x > 1.f) ? 1.f : 0.f;  m.x = (m.x > 1.f) ? 0.f : m.x;
            float py = (m.y > 1.f) ? 1.f : 0.f;  m.y = (m.y > 1.f) ? 0.f : m.y;
            float pz = (m.z > 1.f) ? 1.f : 0.f;  m.z = (m.z > 1.f) ? 0.f : m.z;
            float pw = (m.w > 1.f) ? 1.f : 0.f;  m.w = (m.w > 1.f) ? 0.f : m.w;
            *(float4*)(g_m0 + ix) = m;
            __nv_bfloat162* sp2 = (__nv_bfloat162*)(g_spk0 + ix);
            sp2[0] = __floats2bfloat162_rn(px, py);
            sp2[1] = __floats2bfloat162_rn(pz, pw);
        }
    }
}

// ============================================================
// launch
// ============================================================
extern "C" void kernel_launch(void* const* d_in, const int* in_sizes, int n_in,
                              void* d_out, int out_size) {
    (void)in_sizes; (void)n_in; (void)out_size;
    const float* inp = (const float*)d_in[0];   // [16384, 128]
    const float* W0  = (const float*)d_in[1];   // [256, 512]
    const float* W1  = (const float*)d_in[2];   // [512, 512]
    const float* W2  = (const float*)d_in[3];   // [512, 512]
    float* out = (float*)d_out;                 // m2 state [16384, 512]

    cudaFuncSetAttribute(gemm_mma<1>, cudaFuncAttributeMaxDynamicSharedMemorySize, SMEM_NEED);
    cudaFuncSetAttribute(gemm_mma<2>, cudaFuncAttributeMaxDynamicSharedMemorySize, SMEM_NEED);

    const int EW_BLOCKS = (NELEM / 4) / 256;    // 8192

    zero_kernel<<<EW_BLOCKS, 256>>>((float4*)out);
    prep_kernel<1><<<1024, 256>>>(W1);
    prep_kernel<2><<<1024, 256>>>(W2);
    gemm0_kernel<<<dim3(BATCH / 128, 4), 256>>>(inp, W0);
    step0_kernel<<<EW_BLOCKS, 256>>>();

    dim3 grid(BATCH / 128, 4);
    for (int t = 0; t < NSTEP; t++) {
        gemm_mma<1><<<grid, 256, SMEM_NEED>>>(nullptr);
        gemm_mma<2><<<grid, 256, SMEM_NEED>>>(out);
    }
}

// round 4
// speedup vs baseline: 2.1642x; 1.2351x over previous
#include <cuda_runtime.h>
#include <cuda_bf16.h>
#include <cstdint>

// ============================================================
// 3-layer SNN. B=16384, H=512, 127 steps.
// h0 = relu_concat(x) @ W0 time-invariant (once, fp32 SIMT).
// Per step: spk0@W1 + LIF -> spk1 ; spk1@W2 + LIF -> m2 (+ fused layer-0 LIF).
// Engine: mma.sync m16n8k16 bf16 HMMA, exact 3-way bf16 split of W.
// R4: 2 CTAs/SM (96KB smem, 3-stage K=32 pipeline, SW64 swizzle),
//     register-direct fused epilogue, layer-0 LIF overlapped with fill.
// ============================================================

constexpr int BATCH = 16384;
constexpr int NSTEP = 127;
#define NELEM (16384 * 512)

__device__ float g_h0[NELEM];
__device__ float g_m0[NELEM];
__device__ float g_s1[NELEM];
__device__ float g_m1[NELEM];
__device__ float g_s2[NELEM];
__device__ __nv_bfloat16 g_spk0[NELEM];
__device__ __nv_bfloat16 g_spk1[NELEM];
__device__ __nv_bfloat16 g_W1t[3][512 * 512];   // [split][N][K] K-contiguous
__device__ __nv_bfloat16 g_W2t[3][512 * 512];

// ---- PTX helpers (sm_80-class, valid at sm_103 base target) ----
__device__ __forceinline__ uint32_t smem_to_u32(const void* p) {
    uint32_t a;
    asm("{ .reg .u64 t; cvta.to.shared.u64 t, %1; cvt.u32.u64 %0, t; }"
        : "=r"(a) : "l"(p));
    return a;
}
__device__ __forceinline__ void cp16(uint32_t dst, const void* src) {
    asm volatile("cp.async.cg.shared.global [%0], [%1], 16;"
                 :: "r"(dst), "l"(src) : "memory");
}
#define CP_COMMIT() asm volatile("cp.async.commit_group;" ::: "memory")
#define CP_WAIT(N)  asm volatile("cp.async.wait_group %0;" :: "n"(N) : "memory")

__device__ __forceinline__ void ldm4(uint32_t& r0, uint32_t& r1, uint32_t& r2,
                                     uint32_t& r3, uint32_t addr) {
    asm volatile("ldmatrix.sync.aligned.m8n8.x4.shared.b16 {%0,%1,%2,%3}, [%4];"
                 : "=r"(r0), "=r"(r1), "=r"(r2), "=r"(r3) : "r"(addr));
}
__device__ __forceinline__ void mma16816(float* c, const uint32_t* a,
                                         uint32_t b0, uint32_t b1) {
    asm volatile(
        "mma.sync.aligned.m16n8k16.row.col.f32.bf16.bf16.f32 "
        "{%0,%1,%2,%3}, {%4,%5,%6,%7}, {%8,%9}, {%0,%1,%2,%3};"
        : "+f"(c[0]), "+f"(c[1]), "+f"(c[2]), "+f"(c[3])
        : "r"(a[0]), "r"(a[1]), "r"(a[2]), "r"(a[3]), "r"(b0), "r"(b1));
}
// SW64 swizzle for 64-byte rows (8 rows x 64B atom): conflict-free ldmatrix
#define SWZ64(x) ((x) ^ (((x) >> 3) & 0x30))

// ============================================================
// one-time kernels
// ============================================================
__global__ void zero_kernel(float4* __restrict__ out) {
    int i = blockIdx.x * blockDim.x + threadIdx.x;
    float4 z = make_float4(0.f, 0.f, 0.f, 0.f);
    ((float4*)g_m0)[i] = z;
    ((float4*)g_s1)[i] = z;
    ((float4*)g_m1)[i] = z;
    ((float4*)g_s2)[i] = z;
    out[i] = z;
}

template <int WHICH>
__global__ void prep_kernel(const float* __restrict__ Wsrc) {
    int idx = blockIdx.x * blockDim.x + threadIdx.x;  // over 512*512
    int k = idx >> 9, n = idx & 511;
    float w = Wsrc[idx];
    __nv_bfloat16 hi = __float2bfloat16(w);
    float r1 = w - __bfloat162float(hi);
    __nv_bfloat16 mid = __float2bfloat16(r1);
    float r2 = r1 - __bfloat162float(mid);
    __nv_bfloat16 lo = __float2bfloat16(r2);
    __nv_bfloat16 (*dst)[512 * 512] = (WHICH == 1) ? g_W1t : g_W2t;
    int t = n * 512 + k;
    dst[0][t] = hi;
    dst[1][t] = mid;
    dst[2][t] = lo;
}

__global__ void step0_kernel() {
    int i = blockIdx.x * blockDim.x + threadIdx.x;
    float4 h = ((const float4*)g_h0)[i];
    float4 m = ((const float4*)g_m0)[i];
    m.x = 0.85f * m.x + h.x;  m.y = 0.85f * m.y + h.y;
    m.z = 0.85f * m.z + h.z;  m.w = 0.85f * m.w + h.w;
    float sx = (m.x > 1.f) ? 1.f : 0.f;  m.x = (m.x > 1.f) ? 0.f : m.x;
    float sy = (m.y > 1.f) ? 1.f : 0.f;  m.y = (m.y > 1.f) ? 0.f : m.y;
    float sz = (m.z > 1.f) ? 1.f : 0.f;  m.z = (m.z > 1.f) ? 0.f : m.z;
    float sw = (m.w > 1.f) ? 1.f : 0.f;  m.w = (m.w > 1.f) ? 0.f : m.w;
    ((float4*)g_m0)[i] = m;
    __nv_bfloat162* sp = (__nv_bfloat162*)(g_spk0 + 4 * (size_t)i);
    sp[0] = __floats2bfloat162_rn(sx, sy);
    sp[1] = __floats2bfloat162_rn(sz, sw);
}

// ============================================================
// layer-0 drive: h0 = relu_concat(inputs) @ W0 (fp32, runs once)
// ============================================================
__global__ __launch_bounds__(256)
void gemm0_kernel(const float* __restrict__ Aext, const float* __restrict__ W) {
    constexpr int KT = 8, NK = 256 / KT;
    __shared__ float As[2][KT][128];
    __shared__ float Bs[2][KT][128];
    const int row0 = blockIdx.x * 128, col0 = blockIdx.y * 128;
    const int tid = threadIdx.x;
    const int tx = tid & 15, ty = tid >> 4;
    const int ar = tid >> 1, aq = (tid & 1) * 4;
    const int bk = tid >> 5, bj = (tid & 31) * 4;

    float acc[8][8];
#pragma unroll
    for (int i = 0; i < 8; i++)
#pragma unroll
        for (int j = 0; j < 8; j++) acc[i][j] = 0.f;

    float4 ra, rb;
    auto LOADG = [&](int k0) {
        int kk = k0 + aq;
        if (kk < 128) {
            float4 v = *(const float4*)(Aext + (size_t)(row0 + ar) * 128 + kk);
            ra.x = fmaxf(v.x, 0.f); ra.y = fmaxf(v.y, 0.f);
            ra.z = fmaxf(v.z, 0.f); ra.w = fmaxf(v.w, 0.f);
        } else {
            float4 v = *(const float4*)(Aext + (size_t)(row0 + ar) * 128 + (kk - 128));
            ra.x = fmaxf(-v.x, 0.f); ra.y = fmaxf(-v.y, 0.f);
            ra.z = fmaxf(-v.z, 0.f); ra.w = fmaxf(-v.w, 0.f);
        }
        rb = *(const float4*)(W + (size_t)(k0 + bk) * 512 + col0 + bj);
    };
    auto STORES = [&](int buf) {
        As[buf][aq + 0][ar] = ra.x; As[buf][aq + 1][ar] = ra.y;
        As[buf][aq + 2][ar] = ra.z; As[buf][aq + 3][ar] = ra.w;
        *(float4*)&Bs[buf][bk][bj] = rb;
    };

    LOADG(0); STORES(0); __syncthreads();
    for (int kt = 0; kt < NK; kt++) {
        const int buf = kt & 1;
        if (kt + 1 < NK) LOADG((kt + 1) * KT);
#pragma unroll
        for (int k = 0; k < KT; k++) {
            float4 a0 = *(const float4*)&As[buf][k][ty * 8];
            float4 a1 = *(const float4*)&As[buf][k][ty * 8 + 4];
            float4 b0 = *(const float4*)&Bs[buf][k][tx * 8];
            float4 b1 = *(const float4*)&Bs[buf][k][tx * 8 + 4];
            float av[8] = {a0.x, a0.y, a0.z, a0.w, a1.x, a1.y, a1.z, a1.w};
            float bv[8] = {b0.x, b0.y, b0.z, b0.w, b1.x, b1.y, b1.z, b1.w};
#pragma unroll
            for (int i = 0; i < 8; i++)
#pragma unroll
                for (int j = 0; j < 8; j++) acc[i][j] = fmaf(av[i], bv[j], acc[i][j]);
        }
        if (kt + 1 < NK) STORES(buf ^ 1);
        __syncthreads();
    }
    const int r0 = row0 + ty * 8, c0 = col0 + tx * 8;
#pragma unroll
    for (int i = 0; i < 8; i++) {
        size_t base = (size_t)(r0 + i) * 512 + c0;
        *(float4*)&g_h0[base]     = make_float4(acc[i][0], acc[i][1], acc[i][2], acc[i][3]);
        *(float4*)&g_h0[base + 4] = make_float4(acc[i][4], acc[i][5], acc[i][6], acc[i][7]);
    }
}

// ============================================================
// HMMA GEMM + fused LIF epilogue (register-direct)
// Tile M=128 x N=128; K=512 in 16 chunks of 32; 3 bf16 W-splits.
// 3-stage cp.async pipeline, 32KB/stage (A 8KB + B 3x8KB), SW64 swizzle.
// 8 warps: warp_m = wid&3 (32 rows), warp_n = wid>>2 (64 cols).
// ============================================================
constexpr int STAGE_BYTES = 32768;
constexpr int SMEM_NEED   = 3 * STAGE_BYTES;   // 96KB -> 2 CTAs/SM

template <int MODE>
__global__ __launch_bounds__(256, 2)
void gemm_mma(float* __restrict__ Mext) {
    extern __shared__ char smem[];
    const int tid = threadIdx.x;
    const int wid = tid >> 5, lane = tid & 31;
    const int warp_m = wid & 3, warp_n = wid >> 2;
    const int row0 = blockIdx.x * 128, col0 = blockIdx.y * 128;

    const __nv_bfloat16* A = (MODE == 1) ? g_spk0 : g_spk1;
    const __nv_bfloat16* W = (MODE == 1) ? &g_W1t[0][0] : &g_W2t[0][0];

    const uint32_t sb = smem_to_u32(smem);

    // ---- async chunk staging: A[128r][32k], B[3][128n][32k], SW64 ----
    auto load_chunk = [&](int c, int s) {
        const uint32_t ap = sb + s * STAGE_BYTES;
        const uint32_t bp = ap + 8192;
        const int k0 = c * 32;
#pragma unroll
        for (int j = 0; j < 2; j++) {                  // A: 512 x 16B
            int i = tid + j * 256;
            int r = i >> 2, q = i & 3;
            cp16(ap + SWZ64(r * 64 + q * 16),
                 A + (size_t)(row0 + r) * 512 + k0 + q * 8);
        }
#pragma unroll
        for (int j = 0; j < 6; j++) {                  // B: 3 x 512 x 16B
            int i = tid + j * 256;
            int sp = i >> 9, rem = i & 511;
            int n = rem >> 2, q = rem & 3;
            cp16(bp + sp * 8192 + SWZ64(n * 64 + q * 16),
                 W + (size_t)sp * 262144 + (size_t)(col0 + n) * 512 + k0 + q * 8);
        }
        CP_COMMIT();
    };

    load_chunk(0, 0);
    load_chunk(1, 1);

    // ---- MODE 2: layer-0 LIF for NEXT step (overlaps pipeline fill) ----
    if (MODE == 2) {
#pragma unroll
        for (int j = 0; j < 16; j++) {
            int v = tid + j * 256;
            int rr = v >> 5, cc = (v & 31) << 2;
            size_t ix = (size_t)(row0 + rr) * 512 + col0 + cc;
            float4 h = *(const float4*)(g_h0 + ix);
            float4 m = *(const float4*)(g_m0 + ix);
            m.x = 0.85f * m.x + h.x;  m.y = 0.85f * m.y + h.y;
            m.z = 0.85f * m.z + h.z;  m.w = 0.85f * m.w + h.w;
            float px = (m.x > 1.f) ? 1.f : 0.f;  m.x = (m.x > 1.f) ? 0.f : m.x;
            float py = (m.y > 1.f) ? 1.f : 0.f;  m.y = (m.y > 1.f) ? 0.f : m.y;
            float pz = (m.z > 1.f) ? 1.f : 0.f;  m.z = (m.z > 1.f) ? 0.f : m.z;
            float pw = (m.w > 1.f) ? 1.f : 0.f;  m.w = (m.w > 1.f) ? 0.f : m.w;
            *(float4*)(g_m0 + ix) = m;
            __nv_bfloat162* sp2 = (__nv_bfloat162*)(g_spk0 + ix);
            sp2[0] = __floats2bfloat162_rn(px, py);
            sp2[1] = __floats2bfloat162_rn(pz, pw);
        }
    }

    float acc[2][8][4];
#pragma unroll
    for (int mt = 0; mt < 2; mt++)
#pragma unroll
        for (int nb = 0; nb < 8; nb++)
#pragma unroll
            for (int e = 0; e < 4; e++) acc[mt][nb][e] = 0.f;

    const int mat = lane >> 3, mrr = lane & 7;

#pragma unroll 1
    for (int c = 0; c < 16; c++) {
        const int s = c % 3;
        if (c < 15) CP_WAIT(1); else CP_WAIT(0);
        __syncthreads();
        if (c + 2 < 16) load_chunk(c + 2, (c + 2) % 3);

        const uint32_t ab = sb + s * STAGE_BYTES;
        const uint32_t bb = ab + 8192;
#pragma unroll
        for (int k16 = 0; k16 < 2; k16++) {
            const int k0 = k16 * 16;
            uint32_t a[2][4];
#pragma unroll
            for (int mt = 0; mt < 2; mt++) {
                int row = warp_m * 32 + mt * 16 + (mat & 1) * 8 + mrr;
                int kk  = k0 + (mat >> 1) * 8;
                ldm4(a[mt][0], a[mt][1], a[mt][2], a[mt][3],
                     ab + SWZ64(row * 64 + kk * 2));
            }
#pragma unroll
            for (int sp = 0; sp < 3; sp++) {
                uint32_t b[4][4];
#pragma unroll
                for (int nt = 0; nt < 4; nt++) {
                    int n  = warp_n * 64 + nt * 16 + (mat >> 1) * 8 + mrr;
                    int kk = k0 + (mat & 1) * 8;
                    ldm4(b[nt][0], b[nt][1], b[nt][2], b[nt][3],
                         bb + sp * 8192 + SWZ64(n * 64 + kk * 2));
                }
#pragma unroll
                for (int mt = 0; mt < 2; mt++)
#pragma unroll
                    for (int nb = 0; nb < 8; nb++)
                        mma16816(acc[mt][nb], a[mt],
                                 b[nb >> 1][(nb & 1) * 2],
                                 b[nb >> 1][(nb & 1) * 2 + 1]);
            }
        }
        __syncthreads();
    }

    // ---- fused LIF epilogue, direct from mma fragments ----
    // fragment (mt,nb): rows r, r+8; cols c..c+1 (float2, lanes 32B-contig)
    float* S = (MODE == 1) ? g_s1 : g_s2;
    float* M = (MODE == 1) ? g_m1 : Mext;
    const int er = row0 + warp_m * 32 + (lane >> 2);
    const int ec = col0 + warp_n * 64 + (lane & 3) * 2;
#pragma unroll
    for (int mt = 0; mt < 2; mt++)
#pragma unroll
        for (int nb = 0; nb < 8; nb++)
#pragma unroll
            for (int hrow = 0; hrow < 2; hrow++) {
                size_t ix = (size_t)(er + mt * 16 + hrow * 8) * 512 + ec + nb * 8;
                float2 sv = *(const float2*)(S + ix);
                float2 mv = *(const float2*)(M + ix);
                float hx = acc[mt][nb][hrow * 2 + 0];
                float hy = acc[mt][nb][hrow * 2 + 1];
                sv.x = 0.9f * sv.x + hx;  mv.x = 0.85f * mv.x + sv.x;
                sv.y = 0.9f * sv.y + hy;  mv.y = 0.85f * mv.y + sv.y;
                if (MODE == 1) {
                    float px = (mv.x > 1.f) ? 1.f : 0.f;  mv.x = (mv.x > 1.f) ? 0.f : mv.x;
                    float py = (mv.y > 1.f) ? 1.f : 0.f;  mv.y = (mv.y > 1.f) ? 0.f : mv.y;
                    *(__nv_bfloat162*)(g_spk1 + ix) = __floats2bfloat162_rn(px, py);
                }
                *(float2*)(S + ix) = sv;
                *(float2*)(M + ix) = mv;
            }
}

// ============================================================
// launch
// ============================================================
extern "C" void kernel_launch(void* const* d_in, const int* in_sizes, int n_in,
                              void* d_out, int out_size) {
    (void)in_sizes; (void)n_in; (void)out_size;
    const float* inp = (const float*)d_in[0];   // [16384, 128]
    const float* W0  = (const float*)d_in[1];   // [256, 512]
    const float* W1  = (const float*)d_in[2];   // [512, 512]
    const float* W2  = (const float*)d_in[3];   // [512, 512]
    float* out = (float*)d_out;                 // m2 state [16384, 512]

    cudaFuncSetAttribute(gemm_mma<1>, cudaFuncAttributeMaxDynamicSharedMemorySize, SMEM_NEED);
    cudaFuncSetAttribute(gemm_mma<2>, cudaFuncAttributeMaxDynamicSharedMemorySize, SMEM_NEED);

    const int EW_BLOCKS = (NELEM / 4) / 256;    // 8192

    zero_kernel<<<EW_BLOCKS, 256>>>((float4*)out);
    prep_kernel<1><<<1024, 256>>>(W1);
    prep_kernel<2><<<1024, 256>>>(W2);
    gemm0_kernel<<<dim3(BATCH / 128, 4), 256>>>(inp, W0);
    step0_kernel<<<EW_BLOCKS, 256>>>();

    dim3 grid(BATCH / 128, 4);
    for (int t = 0; t < NSTEP; t++) {
        gemm_mma<1><<<grid, 256, SMEM_NEED>>>(nullptr);
        gemm_mma<2><<<grid, 256, SMEM_NEED>>>(out);
    }
}